// round 11
// baseline (speedup 1.0000x reference)
#include <cuda_runtime.h>
#include <cuda_bf16.h>

#define Bb   16
#define Nn   8
#define Tt   65536
#define CPB  32            // chunks per batch
#define TPB  128
#define NVALS 80           // 64 gram + 8 sum(x^2) + 8 sum(y^2)
#define ITERS ((Tt / CPB) / 4 / TPB)   // = 4 float4 iterations per thread
#define GRID (Bb * CPB)    // 512 blocks

// Partials laid out [batch][value][chunk] -> tail reduces contiguous 128B runs.
// No float atomics anywhere -> deterministic.
__device__ float g_partial[Bb * NVALS * CPB];
__device__ unsigned int g_count = 0;

__device__ __forceinline__ float dot4(float4 a, float4 b) {
    return a.x * b.x + a.y * b.y + a.z * b.z + a.w * b.w;
}

// ---------------------------------------------------------------------------
// Fused kernel = proven parts only:
//  * Gram loop: EXACT R2 scalar float4 version — measured 10us in-run,
//    178 regs NO spill at occ=2 (R9 profile). FFMA2 variants measured 2x
//    slower (RF-banking rt penalty) — rejected for good.
//  * Fusion shell: R10's last-block election + launch_bounds(128,2) -> 255
//    reg budget, which R10 proved avoids R3's 142-reg spill.
//  * Tail: R10's contiguous Phase-A reduction + thread-per-(batch,row)
//    linear-domain Sinkhorn (correctness-proven, rel_err ~1.3e-6).
// Deletes the ~11us sink+launch-gap residual of the two-kernel versions.
// ---------------------------------------------------------------------------
__global__ __launch_bounds__(TPB, 2) void k_fused(const float* __restrict__ inp,
                                                  const float* __restrict__ tgt,
                                                  float* __restrict__ out,
                                                  int out_size) {
    const int b   = blockIdx.x / CPB;
    const int c   = blockIdx.x % CPB;
    const int tid = threadIdx.x;

    // ---------------- Gram partials (scalar, R2 loop) ----------------
    {
        const float4* ip = reinterpret_cast<const float4*>(inp) + (size_t)b * Nn * (Tt / 4);
        const float4* tp = reinterpret_cast<const float4*>(tgt) + (size_t)b * Nn * (Tt / 4);
        const int base = c * (Tt / CPB / 4) + tid;

        float acc[NVALS];
#pragma unroll
        for (int v = 0; v < NVALS; v++) acc[v] = 0.f;

#pragma unroll
        for (int k = 0; k < ITERS; k++) {
            const int idx = base + k * TPB;
            float4 av[Nn], bv[Nn];
#pragma unroll
            for (int i = 0; i < Nn; i++) av[i] = ip[i * (Tt / 4) + idx];
#pragma unroll
            for (int j = 0; j < Nn; j++) bv[j] = tp[j * (Tt / 4) + idx];
#pragma unroll
            for (int i = 0; i < Nn; i++) acc[64 + i] += dot4(av[i], av[i]);
#pragma unroll
            for (int j = 0; j < Nn; j++) acc[72 + j] += dot4(bv[j], bv[j]);
#pragma unroll
            for (int i = 0; i < Nn; i++)
#pragma unroll
                for (int j = 0; j < Nn; j++)
                    acc[i * 8 + j] += dot4(av[i], bv[j]);
        }

        // Fixed-order reduction: warp shuffle then cross-warp via smem.
        __shared__ float sm[TPB / 32][NVALS];
        const int lane = tid & 31, warp = tid >> 5;
#pragma unroll
        for (int v = 0; v < NVALS; v++) {
            float x = acc[v];
#pragma unroll
            for (int off = 16; off; off >>= 1) x += __shfl_down_sync(0xffffffffu, x, off);
            if (lane == 0) sm[warp][v] = x;
        }
        __syncthreads();
        if (tid < NVALS) {
            float s = 0.f;
#pragma unroll
            for (int w = 0; w < TPB / 32; w++) s += sm[w][tid];
            g_partial[(b * NVALS + tid) * CPB + c] = s;   // [b][val][chunk]
        }
    }

    // ---------------- Last-block election ----------------
    __shared__ int is_last;
    __syncthreads();
    if (tid == 0) {
        __threadfence();                                  // publish partials
        unsigned int prev = atomicAdd(&g_count, 1u);
        is_last = (prev == GRID - 1);
        if (is_last) g_count = 0;                         // reset for replay
    }
    __syncthreads();
    if (!is_last) return;
    __threadfence();                                      // acquire partials

    // ---------------- Tail: reduce + Sinkhorn ----------------
    __shared__ float G[Bb][NVALS];
    __shared__ float lsum[TPB];

    for (int v = tid; v < Bb * NVALS; v += TPB) {
        const float4* p = reinterpret_cast<const float4*>(&g_partial[v * CPB]);
        float s = 0.f;
#pragma unroll
        for (int q = 0; q < CPB / 4; q++) {
            const float4 x = p[q];
            s += x.x + x.y + x.z + x.w;
        }
        G[v / NVALS][v % NVALS] = s;
    }
    __syncthreads();

    const int bb = tid >> 3;            // batch (16)
    const int i  = tid & 7;             // row   (8)
    const float invT = 1.0f / (float)Tt;

    float L[Nn], P[Nn];
    const float sxi = G[bb][64 + i];
#pragma unroll
    for (int j = 0; j < Nn; j++) {
        L[j] = (sxi + G[bb][72 + j] - 2.f * G[bb][i * 8 + j]) * invT;
        P[j] = __expf(-L[j]);           // P = exp(-COLDNESS*L)
    }

    // Linear-domain Sinkhorn: col-normalize (shfl over the 8 rows of this
    // batch = 8 consecutive lanes) then row-normalize (in-thread). 10x.
#pragma unroll
    for (int it = 0; it < 10; it++) {
        float cs[Nn];
#pragma unroll
        for (int j = 0; j < Nn; j++) cs[j] = P[j];
#pragma unroll
        for (int off = 1; off <= 4; off <<= 1)
#pragma unroll
            for (int j = 0; j < Nn; j++)
                cs[j] += __shfl_xor_sync(0xffffffffu, cs[j], off);
#pragma unroll
        for (int j = 0; j < Nn; j++) P[j] *= __fdividef(1.f, cs[j]);

        float rs = 0.f;
#pragma unroll
        for (int j = 0; j < Nn; j++) rs += P[j];
        const float rr = __fdividef(1.f, rs);
#pragma unroll
        for (int j = 0; j < Nn; j++) P[j] *= rr;
    }

    // Loss: sum_j (L + ln P) * P per row; argmax_j P (first occurrence,
    // matching jnp.argmax).
    float lp = 0.f;
    int best = 0;
    float bv = P[0];
#pragma unroll
    for (int j = 0; j < Nn; j++) {
        lp += (L[j] + __logf(P[j])) * P[j];
        if (P[j] > bv) { bv = P[j]; best = j; }
    }
    lsum[tid] = lp;
    if (out_size >= 1 + Bb * Nn) out[1 + tid] = (float)best;
    __syncthreads();

    if (tid == 0) {
        float s = 0.f;
#pragma unroll
        for (int k = 0; k < TPB; k++) s += lsum[k];
        out[0] = s * (1.0f / (float)Bb);
    }
}

// ---------------------------------------------------------------------------
extern "C" void kernel_launch(void* const* d_in, const int* in_sizes, int n_in,
                              void* d_out, int out_size) {
    const float* inp = (const float*)d_in[0];
    const float* tgt = (const float*)d_in[1];
    k_fused<<<GRID, TPB>>>(inp, tgt, (float*)d_out, out_size);
}

// round 12
// speedup vs baseline: 1.5849x; 1.5849x over previous
#include <cuda_runtime.h>
#include <cuda_bf16.h>

#define Bb   16
#define Nn   8
#define Tt   65536
#define CPB  32            // chunks per batch
#define TPB  128
#define NVALS 80           // 64 gram + 8 sum(x^2) + 8 sum(y^2)
#define ITERS ((Tt / CPB) / 4 / TPB)   // = 4 float4 iterations per thread
#define GRID (Bb * CPB)

// Partials laid out [batch][value][chunk]: k_sink's Phase A reduces a
// contiguous 128B line per output (R2's [block][val] layout made Phase A
// ~40960 scattered 32B-sector refills into ONE SM ~= 9-14us — the real
// sink cost). No atomics anywhere -> deterministic.
__device__ float g_partial[Bb * NVALS * CPB];

__device__ __forceinline__ float dot4(float4 a, float4 b) {
    return a.x * b.x + a.y * b.y + a.z * b.z + a.w * b.w;
}

// ---------------------------------------------------------------------------
// Kernel 1: EXACT R2 gram (no launch_bounds minBlocks — the config measured
// at 178 regs, no spill, ~10us in-run). The ONLY change vs R2 is the final
// cold store line (transposed layout), outside the hot loop.
// ---------------------------------------------------------------------------
__global__ __launch_bounds__(TPB) void k_gram(const float* __restrict__ inp,
                                              const float* __restrict__ tgt) {
    const int b   = blockIdx.x / CPB;
    const int c   = blockIdx.x % CPB;
    const int tid = threadIdx.x;

    const float4* ip = reinterpret_cast<const float4*>(inp) + (size_t)b * Nn * (Tt / 4);
    const float4* tp = reinterpret_cast<const float4*>(tgt) + (size_t)b * Nn * (Tt / 4);
    const int base = c * (Tt / CPB / 4) + tid;

    float acc[NVALS];
#pragma unroll
    for (int v = 0; v < NVALS; v++) acc[v] = 0.f;

#pragma unroll
    for (int k = 0; k < ITERS; k++) {
        const int idx = base + k * TPB;
        float4 av[Nn], bv[Nn];
#pragma unroll
        for (int i = 0; i < Nn; i++) av[i] = ip[i * (Tt / 4) + idx];
#pragma unroll
        for (int j = 0; j < Nn; j++) bv[j] = tp[j * (Tt / 4) + idx];
#pragma unroll
        for (int i = 0; i < Nn; i++) acc[64 + i] += dot4(av[i], av[i]);
#pragma unroll
        for (int j = 0; j < Nn; j++) acc[72 + j] += dot4(bv[j], bv[j]);
#pragma unroll
        for (int i = 0; i < Nn; i++)
#pragma unroll
            for (int j = 0; j < Nn; j++)
                acc[i * 8 + j] += dot4(av[i], bv[j]);
    }

    // Fixed-order reduction: warp shuffle then cross-warp via smem.
    __shared__ float sm[TPB / 32][NVALS];
    const int lane = tid & 31, warp = tid >> 5;
#pragma unroll
    for (int v = 0; v < NVALS; v++) {
        float x = acc[v];
#pragma unroll
        for (int off = 16; off; off >>= 1) x += __shfl_down_sync(0xffffffffu, x, off);
        if (lane == 0) sm[warp][v] = x;
    }
    __syncthreads();
    if (tid < NVALS) {
        float s = 0.f;
#pragma unroll
        for (int w = 0; w < TPB / 32; w++) s += sm[w][tid];
        g_partial[(b * NVALS + tid) * CPB + c] = s;   // [b][val][chunk]
    }
}

// ---------------------------------------------------------------------------
// Kernel 2: EXACT R5 sink. 512 threads. Phase A: contiguous 32-float
// (one 128B line) reduction per output via 8 float4 loads. Phase B: one warp
// per batch, linear-domain Sinkhorn entirely in registers + shuffles.
// ---------------------------------------------------------------------------
__global__ __launch_bounds__(512) void k_sink(float* __restrict__ out, int out_size) {
    __shared__ float G[Bb][NVALS];
    __shared__ float bloss[Bb];

    const int tid = threadIdx.x;

    // Phase A: 1280 outputs over 512 threads; contiguous reduction.
    for (int v = tid; v < Bb * NVALS; v += 512) {
        const float4* p = reinterpret_cast<const float4*>(&g_partial[v * CPB]);
        float s = 0.f;
#pragma unroll
        for (int q = 0; q < CPB / 4; q++) {
            const float4 x = p[q];
            s += x.x + x.y + x.z + x.w;
        }
        G[v / NVALS][v % NVALS] = s;
    }
    __syncthreads();

    // Phase B: warp w = batch w; lane layout (i0 = lane>>3 and i0+4) x (j = lane&7).
    const int w  = tid >> 5;
    const int l  = tid & 31;
    const int j  = l & 7;
    const int i0 = l >> 3;
    const int i1 = i0 + 4;
    const float invT = 1.0f / (float)Tt;

    if (w < Bb) {
        const float L0 = (G[w][64 + i0] + G[w][72 + j] - 2.f * G[w][i0 * 8 + j]) * invT;
        const float L1 = (G[w][64 + i1] + G[w][72 + j] - 2.f * G[w][i1 * 8 + j]) * invT;
        float p0 = __expf(-L0), p1 = __expf(-L1);   // P = exp(-COLDNESS*L)

        // Linear-domain Sinkhorn: column-normalize then row-normalize, 10x.
#pragma unroll
        for (int it = 0; it < 10; it++) {
            // column sums (over i): lanes {j, 8+j, 16+j, 24+j} x 2 regs
            float s = p0 + p1;
            s += __shfl_xor_sync(0xffffffffu, s, 8);
            s += __shfl_xor_sync(0xffffffffu, s, 16);
            const float r = __fdividef(1.f, s);
            p0 *= r;
            p1 *= r;

            // row sums (over j): 8 consecutive lanes, per register
            float s0 = p0, s1 = p1;
            s0 += __shfl_xor_sync(0xffffffffu, s0, 1);
            s1 += __shfl_xor_sync(0xffffffffu, s1, 1);
            s0 += __shfl_xor_sync(0xffffffffu, s0, 2);
            s1 += __shfl_xor_sync(0xffffffffu, s1, 2);
            s0 += __shfl_xor_sync(0xffffffffu, s0, 4);
            s1 += __shfl_xor_sync(0xffffffffu, s1, 4);
            p0 *= __fdividef(1.f, s0);
            p1 *= __fdividef(1.f, s1);
        }

        // Loss: (L + ln P) * P summed over the matrix, per batch.
        float lp = (L0 + __logf(p0)) * p0 + (L1 + __logf(p1)) * p1;
#pragma unroll
        for (int off = 16; off; off >>= 1) lp += __shfl_xor_sync(0xffffffffu, lp, off);
        if (l == 0) bloss[w] = lp;

        // Argmax over j per row, first occurrence on ties (matches jnp.argmax).
        float v0 = p0, v1 = p1;
        int   a0 = j,  a1 = j;
#pragma unroll
        for (int off = 1; off <= 4; off <<= 1) {
            float ov = __shfl_xor_sync(0xffffffffu, v0, off);
            int   oa = __shfl_xor_sync(0xffffffffu, a0, off);
            if (ov > v0 || (ov == v0 && oa < a0)) { v0 = ov; a0 = oa; }
            ov = __shfl_xor_sync(0xffffffffu, v1, off);
            oa = __shfl_xor_sync(0xffffffffu, a1, off);
            if (ov > v1 || (ov == v1 && oa < a1)) { v1 = ov; a1 = oa; }
        }
        if (out_size >= 1 + Bb * Nn && j == 0) {
            out[1 + w * Nn + i0] = (float)a0;
            out[1 + w * Nn + i1] = (float)a1;
        }
    }

    __syncthreads();
    if (tid == 0) {
        float s = 0.f;
#pragma unroll
        for (int b = 0; b < Bb; b++) s += bloss[b];
        out[0] = s * (1.0f / (float)Bb);
    }
}

// ---------------------------------------------------------------------------
extern "C" void kernel_launch(void* const* d_in, const int* in_sizes, int n_in,
                              void* d_out, int out_size) {
    const float* inp = (const float*)d_in[0];
    const float* tgt = (const float*)d_in[1];
    k_gram<<<GRID, TPB>>>(inp, tgt);
    k_sink<<<1, 512>>>((float*)d_out, out_size);
}

// round 13
// speedup vs baseline: 1.6176x; 1.0206x over previous
#include <cuda_runtime.h>
#include <cuda_bf16.h>

#define Bb   16
#define Nn   8
#define Tt   65536
#define CPB  32              // chunks per batch
#define TPX  128             // t-lanes per block
#define JH   2               // j-halves per block (threadIdx.y)
#define NVALS 80             // 64 gram + 8 sum(x^2) + 8 sum(y^2)
#define NACC  44             // per-thread: 32 cross + 8 sx + 4 sy
#define ITERS ((Tt / CPB) / 4 / TPX)   // = 4 float4 iterations per thread
#define GRID (Bb * CPB)

// Partials [batch][value][chunk] (contiguous per-output reduction in sink).
// No atomics anywhere -> deterministic.
__device__ float g_partial[Bb * NVALS * CPB];

__device__ __forceinline__ float dot4(float4 a, float4 b) {
    return a.x * b.x + a.y * b.y + a.z * b.z + a.w * b.w;
}

// ---------------------------------------------------------------------------
// Kernel 1: gram with j-split for occupancy. R9 profile showed the old shape
// (80 accs, 178 regs) capped at 2 warps/SMSP with the FMA pipe 16% busy —
// pure latency exposure. Here each thread covers all 8 input rows but only
// 4 target rows (threadIdx.y picks the half): 44 accs + 12 load regs ~= 105
// live -> launch_bounds(256,2) = 128-reg budget, no spill, 16 warps/SM =
// 4 warps/SMSP. Inner loop keeps the proven max-MLP shape (12 loads batched).
// Cost: input rows read by both halves (48MB total, still under FFMA floor).
// ---------------------------------------------------------------------------
__global__ __launch_bounds__(TPX * JH, 2) void k_gram(const float* __restrict__ inp,
                                                      const float* __restrict__ tgt) {
    const int b    = blockIdx.x / CPB;
    const int c    = blockIdx.x % CPB;
    const int tidx = threadIdx.x;        // 0..127  (t lane)
    const int y    = threadIdx.y;        // 0..1    (j half)
    const int lt   = y * TPX + tidx;     // linear tid 0..255

    const float4* ip = reinterpret_cast<const float4*>(inp) + (size_t)b * Nn * (Tt / 4);
    const float4* tp = reinterpret_cast<const float4*>(tgt) + (size_t)b * Nn * (Tt / 4)
                     + (size_t)(y * 4) * (Tt / 4);
    const int base = c * (Tt / CPB / 4) + tidx;

    float cr[Nn][4], sx[Nn], sy[4];
#pragma unroll
    for (int i = 0; i < Nn; i++) {
        sx[i] = 0.f;
#pragma unroll
        for (int jj = 0; jj < 4; jj++) cr[i][jj] = 0.f;
    }
#pragma unroll
    for (int jj = 0; jj < 4; jj++) sy[jj] = 0.f;

#pragma unroll
    for (int k = 0; k < ITERS; k++) {
        const int idx = base + k * TPX;
        float4 xv[Nn], yv[4];
#pragma unroll
        for (int i = 0; i < Nn; i++) xv[i] = ip[i * (Tt / 4) + idx];
#pragma unroll
        for (int jj = 0; jj < 4; jj++) yv[jj] = tp[jj * (Tt / 4) + idx];

#pragma unroll
        for (int i = 0; i < Nn; i++) sx[i] += dot4(xv[i], xv[i]);
#pragma unroll
        for (int jj = 0; jj < 4; jj++) sy[jj] += dot4(yv[jj], yv[jj]);
#pragma unroll
        for (int i = 0; i < Nn; i++)
#pragma unroll
            for (int jj = 0; jj < 4; jj++)
                cr[i][jj] += dot4(xv[i], yv[jj]);
    }

    // Pack accs into a flat array: [0,32) cross i*4+jj, [32,40) sx, [40,44) sy.
    float acc[NACC];
#pragma unroll
    for (int i = 0; i < Nn; i++) {
#pragma unroll
        for (int jj = 0; jj < 4; jj++) acc[i * 4 + jj] = cr[i][jj];
        acc[32 + i] = sx[i];
    }
#pragma unroll
    for (int jj = 0; jj < 4; jj++) acc[40 + jj] = sy[jj];

    // Warp shuffle reduce, then cross-warp via smem (warps 0-3: y=0, 4-7: y=1).
    __shared__ float sm[(TPX * JH) / 32][NACC];
    const int lane = lt & 31, warp = lt >> 5;
#pragma unroll
    for (int v = 0; v < NACC; v++) {
        float x = acc[v];
#pragma unroll
        for (int off = 16; off; off >>= 1) x += __shfl_down_sync(0xffffffffu, x, off);
        if (lane == 0) sm[warp][v] = x;
    }
    __syncthreads();

    // 88 (y, val) outputs over 256 threads.
    if (lt < JH * NACC) {
        const int yy = lt / NACC, v = lt % NACC;
        float s = 0.f;
#pragma unroll
        for (int w = 0; w < 4; w++) s += sm[yy * 4 + w][v];

        int val;
        bool wr = true;
        if (v < 32)      val = (v / 4) * 8 + yy * 4 + (v % 4);   // cross G[i][j]
        else if (v < 40) { val = 64 + (v - 32); wr = (yy == 0); } // sum x^2 (dup)
        else             val = 72 + yy * 4 + (v - 40);            // sum y^2
        if (wr) g_partial[(b * NVALS + val) * CPB + c] = s;
    }
}

// ---------------------------------------------------------------------------
// Kernel 2: R12 sink + PDL. cudaGridDependencySynchronize() at the top lets
// this kernel be launched (via programmatic stream serialization) while gram
// is still running — hiding the ~3us kernel-boundary gap measured in R8.
// ---------------------------------------------------------------------------
__global__ __launch_bounds__(512) void k_sink(float* __restrict__ out, int out_size) {
#if defined(__CUDA_ARCH__) && (__CUDA_ARCH__ >= 900)
    cudaGridDependencySynchronize();
#endif

    __shared__ float G[Bb][NVALS];
    __shared__ float bloss[Bb];

    const int tid = threadIdx.x;

    // Phase A: 1280 outputs, each a contiguous 128B run (8 float4 loads).
    for (int v = tid; v < Bb * NVALS; v += 512) {
        const float4* p = reinterpret_cast<const float4*>(&g_partial[v * CPB]);
        float s = 0.f;
#pragma unroll
        for (int q = 0; q < CPB / 4; q++) {
            const float4 x = p[q];
            s += x.x + x.y + x.z + x.w;
        }
        G[v / NVALS][v % NVALS] = s;
    }
    __syncthreads();

    // Phase B: warp w = batch w; lanes = (i0 = l>>3 and i0+4) x (j = l&7).
    const int w  = tid >> 5;
    const int l  = tid & 31;
    const int j  = l & 7;
    const int i0 = l >> 3;
    const int i1 = i0 + 4;
    const float invT = 1.0f / (float)Tt;

    if (w < Bb) {
        const float L0 = (G[w][64 + i0] + G[w][72 + j] - 2.f * G[w][i0 * 8 + j]) * invT;
        const float L1 = (G[w][64 + i1] + G[w][72 + j] - 2.f * G[w][i1 * 8 + j]) * invT;
        float p0 = __expf(-L0), p1 = __expf(-L1);   // P = exp(-COLDNESS*L)

#pragma unroll
        for (int it = 0; it < 10; it++) {
            float s = p0 + p1;
            s += __shfl_xor_sync(0xffffffffu, s, 8);
            s += __shfl_xor_sync(0xffffffffu, s, 16);
            const float r = __fdividef(1.f, s);
            p0 *= r;
            p1 *= r;

            float s0 = p0, s1 = p1;
            s0 += __shfl_xor_sync(0xffffffffu, s0, 1);
            s1 += __shfl_xor_sync(0xffffffffu, s1, 1);
            s0 += __shfl_xor_sync(0xffffffffu, s0, 2);
            s1 += __shfl_xor_sync(0xffffffffu, s1, 2);
            s0 += __shfl_xor_sync(0xffffffffu, s0, 4);
            s1 += __shfl_xor_sync(0xffffffffu, s1, 4);
            p0 *= __fdividef(1.f, s0);
            p1 *= __fdividef(1.f, s1);
        }

        float lp = (L0 + __logf(p0)) * p0 + (L1 + __logf(p1)) * p1;
#pragma unroll
        for (int off = 16; off; off >>= 1) lp += __shfl_xor_sync(0xffffffffu, lp, off);
        if (l == 0) bloss[w] = lp;

        // Argmax over j per row, first occurrence on ties (matches jnp.argmax).
        float v0 = p0, v1 = p1;
        int   a0 = j,  a1 = j;
#pragma unroll
        for (int off = 1; off <= 4; off <<= 1) {
            float ov = __shfl_xor_sync(0xffffffffu, v0, off);
            int   oa = __shfl_xor_sync(0xffffffffu, a0, off);
            if (ov > v0 || (ov == v0 && oa < a0)) { v0 = ov; a0 = oa; }
            ov = __shfl_xor_sync(0xffffffffu, v1, off);
            oa = __shfl_xor_sync(0xffffffffu, a1, off);
            if (ov > v1 || (ov == v1 && oa < a1)) { v1 = ov; a1 = oa; }
        }
        if (out_size >= 1 + Bb * Nn && j == 0) {
            out[1 + w * Nn + i0] = (float)a0;
            out[1 + w * Nn + i1] = (float)a1;
        }
    }

    __syncthreads();
    if (tid == 0) {
        float s = 0.f;
#pragma unroll
        for (int b = 0; b < Bb; b++) s += bloss[b];
        out[0] = s * (1.0f / (float)Bb);
    }
}

// ---------------------------------------------------------------------------
extern "C" void kernel_launch(void* const* d_in, const int* in_sizes, int n_in,
                              void* d_out, int out_size) {
    const float* inp = (const float*)d_in[0];
    const float* tgt = (const float*)d_in[1];

    k_gram<<<GRID, dim3(TPX, JH, 1)>>>(inp, tgt);

    // PDL launch: sink may be scheduled while gram runs; it blocks at
    // cudaGridDependencySynchronize() until gram's writes are visible.
    cudaLaunchAttribute attr[1];
    attr[0].id = cudaLaunchAttributeProgrammaticStreamSerialization;
    attr[0].val.programmaticStreamSerializationAllowed = 1;
    cudaLaunchConfig_t cfg = {};
    cfg.gridDim  = dim3(1, 1, 1);
    cfg.blockDim = dim3(512, 1, 1);
    cfg.dynamicSmemBytes = 0;
    cfg.stream = 0;
    cfg.attrs = attr;
    cfg.numAttrs = 1;
    cudaLaunchKernelEx(&cfg, k_sink, (float*)d_out, out_size);
}

// round 14
// speedup vs baseline: 1.8261x; 1.1289x over previous
#include <cuda_runtime.h>
#include <cuda_bf16.h>

#define Bb   16
#define Nn   8
#define Tt   65536
#define CPB  32            // chunks per batch
#define TPB  128
#define NVALS 80           // 64 gram + 8 sum(x^2) + 8 sum(y^2)
#define ITERS ((Tt / CPB) / 4 / TPB)   // = 4 float4 iterations per thread
#define GRID (Bb * CPB)

// Deterministic scratch (no float atomics). R2 layout: [block][val] — Phase A
// reads are lane-consecutive in val, i.e. already coalesced.
__device__ float g_partial[GRID * NVALS];
__device__ unsigned int g_count = 0;

__device__ __forceinline__ float dot4(float4 a, float4 b) {
    return a.x * b.x + a.y * b.y + a.z * b.z + a.w * b.w;
}

// ---------------------------------------------------------------------------
// Kernel 1: EXACT R2 gram (best measured config). Adds only a release-fence +
// counter increment at the end so the concurrently-resident sink can start
// the tail the moment the last block finishes — no kernel boundary, no
// grid=1 launch/ramp on the critical path.
// ---------------------------------------------------------------------------
__global__ __launch_bounds__(TPB) void k_gram(const float* __restrict__ inp,
                                              const float* __restrict__ tgt) {
    const int b   = blockIdx.x / CPB;
    const int c   = blockIdx.x % CPB;
    const int tid = threadIdx.x;

    const float4* ip = reinterpret_cast<const float4*>(inp) + (size_t)b * Nn * (Tt / 4);
    const float4* tp = reinterpret_cast<const float4*>(tgt) + (size_t)b * Nn * (Tt / 4);
    const int base = c * (Tt / CPB / 4) + tid;

    float acc[NVALS];
#pragma unroll
    for (int v = 0; v < NVALS; v++) acc[v] = 0.f;

#pragma unroll
    for (int k = 0; k < ITERS; k++) {
        const int idx = base + k * TPB;
        float4 av[Nn], bv[Nn];
#pragma unroll
        for (int i = 0; i < Nn; i++) av[i] = ip[i * (Tt / 4) + idx];
#pragma unroll
        for (int j = 0; j < Nn; j++) bv[j] = tp[j * (Tt / 4) + idx];
#pragma unroll
        for (int i = 0; i < Nn; i++) acc[64 + i] += dot4(av[i], av[i]);
#pragma unroll
        for (int j = 0; j < Nn; j++) acc[72 + j] += dot4(bv[j], bv[j]);
#pragma unroll
        for (int i = 0; i < Nn; i++)
#pragma unroll
            for (int j = 0; j < Nn; j++)
                acc[i * 8 + j] += dot4(av[i], bv[j]);
    }

    // Fixed-order reduction: warp shuffle then cross-warp via smem.
    __shared__ float sm[TPB / 32][NVALS];
    const int lane = tid & 31, warp = tid >> 5;
#pragma unroll
    for (int v = 0; v < NVALS; v++) {
        float x = acc[v];
#pragma unroll
        for (int off = 16; off; off >>= 1) x += __shfl_down_sync(0xffffffffu, x, off);
        if (lane == 0) sm[warp][v] = x;
    }
    __syncthreads();
    if (tid < NVALS) {
        float s = 0.f;
#pragma unroll
        for (int w = 0; w < TPB / 32; w++) s += sm[w][tid];
        g_partial[blockIdx.x * NVALS + tid] = s;
    }

    // Publish: release partials, then signal completion.
    __syncthreads();
    if (tid == 0) {
        __threadfence();
        atomicAdd(&g_count, 1u);
    }
}

// ---------------------------------------------------------------------------
// Kernel 2: R2 sink with a spin-wait prologue. Launched CONCURRENTLY with
// gram (forked capture): it sits resident on one SM, spins on g_count, and
// starts the tail the instant the 512th gram block publishes. Deterministic:
// spin count varies, output does not.
// ---------------------------------------------------------------------------
__global__ __launch_bounds__(512) void k_sink(float* __restrict__ out, int out_size) {
    // Wait for all gram blocks.
    if (threadIdx.x == 0) {
        volatile unsigned int* cnt = &g_count;
        while (*cnt < GRID) { __nanosleep(64); }
    }
    __syncthreads();
    __threadfence();   // acquire gram's partials

    __shared__ float G[Bb][NVALS];
    __shared__ float bloss[Bb];

    const int tid = threadIdx.x;

    // Phase A: 1280 (batch,value) outputs over 32 chunks (lane-coalesced).
    for (int v = tid; v < Bb * NVALS; v += 512) {
        const int b = v / NVALS, k = v % NVALS;
        const float* p = &g_partial[b * CPB * NVALS + k];
        float s = 0.f;
#pragma unroll
        for (int c = 0; c < CPB; c++) s += p[c * NVALS];
        G[b][k] = s;
    }
    __syncthreads();

    // Phase B: warp w = batch w; lanes = (i0 = l>>3 and i0+4) x (j = l&7).
    const int w  = tid >> 5;
    const int l  = tid & 31;
    const int j  = l & 7;
    const int i0 = l >> 3;
    const int i1 = i0 + 4;
    const float invT = 1.0f / (float)Tt;

    if (w < Bb) {
        const float L0 = (G[w][64 + i0] + G[w][72 + j] - 2.f * G[w][i0 * 8 + j]) * invT;
        const float L1 = (G[w][64 + i1] + G[w][72 + j] - 2.f * G[w][i1 * 8 + j]) * invT;
        float p0 = __expf(-L0), p1 = __expf(-L1);   // P = exp(-COLDNESS*L)

        // Linear-domain Sinkhorn: column-normalize then row-normalize, 10x.
#pragma unroll
        for (int it = 0; it < 10; it++) {
            float s = p0 + p1;
            s += __shfl_xor_sync(0xffffffffu, s, 8);
            s += __shfl_xor_sync(0xffffffffu, s, 16);
            const float r = __fdividef(1.f, s);
            p0 *= r;
            p1 *= r;

            float s0 = p0, s1 = p1;
            s0 += __shfl_xor_sync(0xffffffffu, s0, 1);
            s1 += __shfl_xor_sync(0xffffffffu, s1, 1);
            s0 += __shfl_xor_sync(0xffffffffu, s0, 2);
            s1 += __shfl_xor_sync(0xffffffffu, s1, 2);
            s0 += __shfl_xor_sync(0xffffffffu, s0, 4);
            s1 += __shfl_xor_sync(0xffffffffu, s1, 4);
            p0 *= __fdividef(1.f, s0);
            p1 *= __fdividef(1.f, s1);
        }

        float lp = (L0 + __logf(p0)) * p0 + (L1 + __logf(p1)) * p1;
#pragma unroll
        for (int off = 16; off; off >>= 1) lp += __shfl_xor_sync(0xffffffffu, lp, off);
        if (l == 0) bloss[w] = lp;

        // Argmax over j per row, first occurrence on ties (matches jnp.argmax).
        float v0 = p0, v1 = p1;
        int   a0 = j,  a1 = j;
#pragma unroll
        for (int off = 1; off <= 4; off <<= 1) {
            float ov = __shfl_xor_sync(0xffffffffu, v0, off);
            int   oa = __shfl_xor_sync(0xffffffffu, a0, off);
            if (ov > v0 || (ov == v0 && oa < a0)) { v0 = ov; a0 = oa; }
            ov = __shfl_xor_sync(0xffffffffu, v1, off);
            oa = __shfl_xor_sync(0xffffffffu, a1, off);
            if (ov > v1 || (ov == v1 && oa < a1)) { v1 = ov; a1 = oa; }
        }
        if (out_size >= 1 + Bb * Nn && j == 0) {
            out[1 + w * Nn + i0] = (float)a0;
            out[1 + w * Nn + i1] = (float)a1;
        }
    }

    __syncthreads();
    if (tid == 0) {
        float s = 0.f;
#pragma unroll
        for (int b = 0; b < Bb; b++) s += bloss[b];
        out[0] = s * (1.0f / (float)Bb);
        g_count = 0;                      // reset for next replay
    }
}

// ---------------------------------------------------------------------------
// Forked launch: sink runs concurrently with gram (event fork/join), so its
// launch + ramp overlap gram execution; synchronization is the device-side
// counter, not a graph edge.
// ---------------------------------------------------------------------------
extern "C" void kernel_launch(void* const* d_in, const int* in_sizes, int n_in,
                              void* d_out, int out_size) {
    const float* inp = (const float*)d_in[0];
    const float* tgt = (const float*)d_in[1];

    static cudaStream_t s2 = nullptr;
    static cudaEvent_t ev_fork = nullptr, ev_join = nullptr;
    if (s2 == nullptr) {
        cudaStreamCreateWithFlags(&s2, cudaStreamNonBlocking);
        cudaEventCreateWithFlags(&ev_fork, cudaEventDisableTiming);
        cudaEventCreateWithFlags(&ev_join, cudaEventDisableTiming);
    }

    // Fork: sink starts concurrently with gram.
    cudaEventRecord(ev_fork, 0);
    cudaStreamWaitEvent(s2, ev_fork, 0);

    k_gram<<<GRID, TPB>>>(inp, tgt);
    k_sink<<<1, 512, 0, s2>>>((float*)d_out, out_size);

    // Join: origin stream waits for the sink.
    cudaEventRecord(ev_join, s2);
    cudaStreamWaitEvent(0, ev_join, 0);
}

// round 15
// speedup vs baseline: 2.0311x; 1.1123x over previous
#include <cuda_runtime.h>
#include <cuda_bf16.h>

#define Bb   16
#define Nn   8
#define Tt   65536
#define TPB  128
#define NVALS 80           // 64 gram + 8 sum(x^2) + 8 sum(y^2)
#define GRID 296           // exactly one resident wave: 148 SMs x 2 blocks (178 regs)
#define NB_HI 19           // blocks for batches 0..7
#define NB_LO 18           // blocks for batches 8..15
#define COLS (Tt / 4)      // 16384 float4 columns per row

// Deterministic scratch (no float atomics). [block][val] layout (R2-proven).
__device__ float g_partial[GRID * NVALS];
__device__ unsigned int g_count = 0;

__device__ __forceinline__ float dot4(float4 a, float4 b) {
    return a.x * b.x + a.y * b.y + a.z * b.z + a.w * b.w;
}

// ---------------------------------------------------------------------------
// Kernel 1: R2 gram body (proven best codegen, 178 regs, no spill) with a
// ONE-WAVE grid: 296 blocks = 148 SMs x 2 resident. The old 512-block grid
// ran 1.73 waves (2nd wave 73% full -> ~13% idle + ramp). Batches 0-7 get 19
// blocks, 8-15 get 18; each block takes a balanced contiguous column range.
// ---------------------------------------------------------------------------
__global__ __launch_bounds__(TPB) void k_gram(const float* __restrict__ inp,
                                              const float* __restrict__ tgt) {
    const int bid = blockIdx.x;
    const int tid = threadIdx.x;

    int b, local, nb;
    if (bid < 8 * NB_HI) { b = bid / NB_HI; local = bid % NB_HI; nb = NB_HI; }
    else { const int r = bid - 8 * NB_HI; b = 8 + r / NB_LO; local = r % NB_LO; nb = NB_LO; }

    const int chunk = COLS / nb, rem = COLS % nb;
    const int start = local * chunk + (local < rem ? local : rem);
    const int end   = start + chunk + (local < rem ? 1 : 0);

    const float4* ip = reinterpret_cast<const float4*>(inp) + (size_t)b * Nn * COLS;
    const float4* tp = reinterpret_cast<const float4*>(tgt) + (size_t)b * Nn * COLS;

    float acc[NVALS];
#pragma unroll
    for (int v = 0; v < NVALS; v++) acc[v] = 0.f;

    for (int idx = start + tid; idx < end; idx += TPB) {
        float4 av[Nn], bv[Nn];
#pragma unroll
        for (int i = 0; i < Nn; i++) av[i] = ip[i * COLS + idx];
#pragma unroll
        for (int j = 0; j < Nn; j++) bv[j] = tp[j * COLS + idx];
#pragma unroll
        for (int i = 0; i < Nn; i++) acc[64 + i] += dot4(av[i], av[i]);
#pragma unroll
        for (int j = 0; j < Nn; j++) acc[72 + j] += dot4(bv[j], bv[j]);
#pragma unroll
        for (int i = 0; i < Nn; i++)
#pragma unroll
            for (int j = 0; j < Nn; j++)
                acc[i * 8 + j] += dot4(av[i], bv[j]);
    }

    // Fixed-order reduction: warp shuffle then cross-warp via smem.
    __shared__ float sm[TPB / 32][NVALS];
    const int lane = tid & 31, warp = tid >> 5;
#pragma unroll
    for (int v = 0; v < NVALS; v++) {
        float x = acc[v];
#pragma unroll
        for (int off = 16; off; off >>= 1) x += __shfl_down_sync(0xffffffffu, x, off);
        if (lane == 0) sm[warp][v] = x;
    }
    __syncthreads();
    if (tid < NVALS) {
        float s = 0.f;
#pragma unroll
        for (int w = 0; w < TPB / 32; w++) s += sm[w][tid];
        g_partial[bid * NVALS + tid] = s;
    }

    // Publish: release partials, then signal completion (R14-proven).
    __syncthreads();
    if (tid == 0) {
        __threadfence();
        atomicAdd(&g_count, 1u);
    }
}

// ---------------------------------------------------------------------------
// Kernel 2: R14 sink (spin-wait prologue; launched concurrently with gram).
// Phase A sums each batch's contiguous block range (19 or 18 blocks).
// ---------------------------------------------------------------------------
__global__ __launch_bounds__(512) void k_sink(float* __restrict__ out, int out_size) {
    if (threadIdx.x == 0) {
        volatile unsigned int* cnt = &g_count;
        while (*cnt < GRID) { __nanosleep(64); }
    }
    __syncthreads();
    __threadfence();   // acquire gram's partials

    __shared__ float G[Bb][NVALS];
    __shared__ float bloss[Bb];

    const int tid = threadIdx.x;

    // Phase A: 1280 (batch,value) outputs; per batch, its block range.
    for (int v = tid; v < Bb * NVALS; v += 512) {
        const int b = v / NVALS, val = v % NVALS;
        const int sb = (b < 8) ? b * NB_HI : 8 * NB_HI + (b - 8) * NB_LO;
        const int nb = (b < 8) ? NB_HI : NB_LO;
        const float* p = &g_partial[sb * NVALS + val];
        float s = 0.f;
        for (int k = 0; k < nb; k++) s += p[k * NVALS];
        G[b][val] = s;
    }
    __syncthreads();

    // Phase B: warp w = batch w; lanes = (i0 = l>>3 and i0+4) x (j = l&7).
    const int w  = tid >> 5;
    const int l  = tid & 31;
    const int j  = l & 7;
    const int i0 = l >> 3;
    const int i1 = i0 + 4;
    const float invT = 1.0f / (float)Tt;

    if (w < Bb) {
        const float L0 = (G[w][64 + i0] + G[w][72 + j] - 2.f * G[w][i0 * 8 + j]) * invT;
        const float L1 = (G[w][64 + i1] + G[w][72 + j] - 2.f * G[w][i1 * 8 + j]) * invT;
        float p0 = __expf(-L0), p1 = __expf(-L1);   // P = exp(-COLDNESS*L)

        // Linear-domain Sinkhorn: column-normalize then row-normalize, 10x.
#pragma unroll
        for (int it = 0; it < 10; it++) {
            float s = p0 + p1;
            s += __shfl_xor_sync(0xffffffffu, s, 8);
            s += __shfl_xor_sync(0xffffffffu, s, 16);
            const float r = __fdividef(1.f, s);
            p0 *= r;
            p1 *= r;

            float s0 = p0, s1 = p1;
            s0 += __shfl_xor_sync(0xffffffffu, s0, 1);
            s1 += __shfl_xor_sync(0xffffffffu, s1, 1);
            s0 += __shfl_xor_sync(0xffffffffu, s0, 2);
            s1 += __shfl_xor_sync(0xffffffffu, s1, 2);
            s0 += __shfl_xor_sync(0xffffffffu, s0, 4);
            s1 += __shfl_xor_sync(0xffffffffu, s1, 4);
            p0 *= __fdividef(1.f, s0);
            p1 *= __fdividef(1.f, s1);
        }

        float lp = (L0 + __logf(p0)) * p0 + (L1 + __logf(p1)) * p1;
#pragma unroll
        for (int off = 16; off; off >>= 1) lp += __shfl_xor_sync(0xffffffffu, lp, off);
        if (l == 0) bloss[w] = lp;

        // Argmax over j per row, first occurrence on ties (matches jnp.argmax).
        float v0 = p0, v1 = p1;
        int   a0 = j,  a1 = j;
#pragma unroll
        for (int off = 1; off <= 4; off <<= 1) {
            float ov = __shfl_xor_sync(0xffffffffu, v0, off);
            int   oa = __shfl_xor_sync(0xffffffffu, a0, off);
            if (ov > v0 || (ov == v0 && oa < a0)) { v0 = ov; a0 = oa; }
            ov = __shfl_xor_sync(0xffffffffu, v1, off);
            oa = __shfl_xor_sync(0xffffffffu, a1, off);
            if (ov > v1 || (ov == v1 && oa < a1)) { v1 = ov; a1 = oa; }
        }
        if (out_size >= 1 + Bb * Nn && j == 0) {
            out[1 + w * Nn + i0] = (float)a0;
            out[1 + w * Nn + i1] = (float)a1;
        }
    }

    __syncthreads();
    if (tid == 0) {
        float s = 0.f;
#pragma unroll
        for (int b = 0; b < Bb; b++) s += bloss[b];
        out[0] = s * (1.0f / (float)Bb);
        g_count = 0;                      // reset for next replay
    }
}

// ---------------------------------------------------------------------------
// Forked launch (R14-proven): sink runs concurrently with gram; device-side
// counter is the real synchronization.
// ---------------------------------------------------------------------------
extern "C" void kernel_launch(void* const* d_in, const int* in_sizes, int n_in,
                              void* d_out, int out_size) {
    const float* inp = (const float*)d_in[0];
    const float* tgt = (const float*)d_in[1];

    static cudaStream_t s2 = nullptr;
    static cudaEvent_t ev_fork = nullptr, ev_join = nullptr;
    if (s2 == nullptr) {
        cudaStreamCreateWithFlags(&s2, cudaStreamNonBlocking);
        cudaEventCreateWithFlags(&ev_fork, cudaEventDisableTiming);
        cudaEventCreateWithFlags(&ev_join, cudaEventDisableTiming);
    }

    cudaEventRecord(ev_fork, 0);
    cudaStreamWaitEvent(s2, ev_fork, 0);

    k_gram<<<GRID, TPB>>>(inp, tgt);
    k_sink<<<1, 512, 0, s2>>>((float*)d_out, out_size);

    cudaEventRecord(ev_join, s2);
    cudaStreamWaitEvent(0, ev_join, 0);
}